// round 8
// baseline (speedup 1.0000x reference)
#include <cuda_runtime.h>
#include <cuda_bf16.h>
#include <cstdint>
#include <cstddef>

// ---------------------------------------------------------------------------
// Problem constants
// B=8, C=384, H=W=32 -> L=1024, M = B*L = 8192 tokens
// D_INNER=768, D_STATE=16, D_CONV=4, DT_RANK=24 (pad 32), x_proj out 56 (pad 128)
// ---------------------------------------------------------------------------
static constexpr int BATCH   = 8;
static constexpr int CCH     = 384;
static constexpr int LSEQ    = 1024;
static constexpr int MTOK    = BATCH * LSEQ;       // 8192
static constexpr int DIN     = 768;
static constexpr int DST     = 16;
static constexpr int DBC_LD  = 128;                // padded x_proj output stride
static constexpr int DTK_LD  = 32;                 // padded dt_rank

// ---------------------------------------------------------------------------
// Scratch (device globals; zero host-side use — all access from device code)
// ---------------------------------------------------------------------------
__device__ __align__(16) float          g_xz  [MTOK * 2 * DIN];
__device__ __align__(16) float          g_u   [MTOK * DIN];
__device__ __align__(16) __nv_bfloat16  g_ubf [MTOK * DIN];
__device__ __align__(16) __nv_bfloat16  g_tok [MTOK * CCH];
__device__ __align__(16) float          g_dbc [MTOK * DBC_LD];
__device__ __align__(16) __nv_bfloat16  g_dtlo[MTOK * DTK_LD];
__device__ __align__(16) float          g_ddot[MTOK * DIN];
__device__ __align__(16) __nv_bfloat16  g_y   [MTOK * DIN];
__device__ __align__(16) float          g_o   [MTOK * CCH];
__device__ __align__(16) __nv_bfloat16  g_win [2 * DIN * CCH];
__device__ __align__(16) __nv_bfloat16  g_wout[CCH * DIN];
__device__ __align__(16) __nv_bfloat16  g_wxp [DBC_LD * DIN];
__device__ __align__(16) __nv_bfloat16  g_wdt [DIN * DTK_LD];

// ---------------------------------------------------------------------------
// Weight conversion fp32 -> bf16 (with zero padding)
// ---------------------------------------------------------------------------
__global__ void convert_weights(const float* __restrict__ win,
                                const float* __restrict__ wout,
                                const float* __restrict__ wxp,
                                const float* __restrict__ wdt) {
    int i = blockIdx.x * 256 + threadIdx.x;
    if (i < 2 * DIN * CCH) g_win[i] = __float2bfloat16(win[i]);
    if (i < CCH * DIN)     g_wout[i] = __float2bfloat16(wout[i]);
    if (i < DBC_LD * DIN)  g_wxp[i] = (i < 56 * DIN) ? __float2bfloat16(wxp[i])
                                                     : __float2bfloat16(0.f);
    if (i < DIN * DTK_LD) {
        int r = i >> 5, c = i & 31;
        g_wdt[i] = (c < 24) ? __float2bfloat16(wdt[r * 24 + c]) : __float2bfloat16(0.f);
    }
}

// ---------------------------------------------------------------------------
// LayerNorm over channels + transpose to token-major bf16 (device-direct g_tok)
// ---------------------------------------------------------------------------
__global__ __launch_bounds__(256)
void ln_kernel(const float* __restrict__ x, const float* __restrict__ lnw,
               const float* __restrict__ lnb) {
    __shared__ float xs[CCH * 17];
    __shared__ float ps[16 * 16], pq[16 * 16];
    __shared__ float mu_s[16], rs_s[16];
    const int b  = blockIdx.y;
    const int l0 = blockIdx.x * 16;
    const int tid = threadIdx.x;

    for (int idx = tid; idx < CCH * 16; idx += 256) {
        int c = idx >> 4, l = idx & 15;
        xs[c * 17 + l] = x[((size_t)b * CCH + c) * LSEQ + l0 + l];
    }
    __syncthreads();
    {
        int l = tid & 15, g = tid >> 4;
        float s = 0.f, q = 0.f;
        for (int c = g; c < CCH; c += 16) {
            float v = xs[c * 17 + l];
            s += v; q += v * v;
        }
        ps[g * 16 + l] = s; pq[g * 16 + l] = q;
    }
    __syncthreads();
    if (tid < 16) {
        float s = 0.f, q = 0.f;
        #pragma unroll
        for (int g = 0; g < 16; g++) { s += ps[g * 16 + tid]; q += pq[g * 16 + tid]; }
        float mu  = s * (1.0f / CCH);
        float var = q * (1.0f / CCH) - mu * mu;
        mu_s[tid] = mu;
        rs_s[tid] = rsqrtf(var + 1e-5f);
    }
    __syncthreads();
    for (int idx = tid; idx < CCH * 16; idx += 256) {
        int c = idx % CCH, l = idx / CCH;
        float v = (xs[c * 17 + l] - mu_s[l]) * rs_s[l] * lnw[c] + lnb[c];
        g_tok[((size_t)b * LSEQ + l0 + l) * CCH + c] = __float2bfloat16(v);
    }
}

// ---------------------------------------------------------------------------
// bf16 tensor-core GEMM:  C[M,N] = A[M,K] * W[N,K]^T, operands chosen by TAG
// in DEVICE code (so __device__ globals resolve to device addresses).
//   TAG 0: g_tok  x g_win  -> g_xz    (K=384, N=1536)
//   TAG 1: g_ubf  x g_wxp  -> g_dbc   (K=768, N=128)
//   TAG 2: g_dtlo x g_wdt  -> g_ddot  (K=32,  N=768)
//   TAG 3: g_y    x g_wout -> g_o     (K=768, N=384)
// Block tile 128x128x32, 256 threads (8 warps, 2m x 4n), warp tile 64x32,
// mma.sync.aligned.m16n8k16 bf16->fp32. All dims padded -> full tiles only.
// ---------------------------------------------------------------------------
__device__ __forceinline__ uint32_t lds32(const __nv_bfloat16* p) {
    return *reinterpret_cast<const uint32_t*>(p);
}
__device__ __forceinline__ void mma16816(float* d, const uint32_t* a, const uint32_t* b) {
    asm volatile(
        "mma.sync.aligned.m16n8k16.row.col.f32.bf16.bf16.f32 "
        "{%0,%1,%2,%3}, {%4,%5,%6,%7}, {%8,%9}, {%0,%1,%2,%3};\n"
        : "+f"(d[0]), "+f"(d[1]), "+f"(d[2]), "+f"(d[3])
        : "r"(a[0]), "r"(a[1]), "r"(a[2]), "r"(a[3]), "r"(b[0]), "r"(b[1]));
}

static constexpr int GBM = 128, GBN = 128, GBK = 32;
static constexpr int SROW = GBK + 8;   // smem row stride (bf16) -> conflict-free

template<int TAG>
__global__ __launch_bounds__(256) void gemm_tc() {
    // ---- device-side operand selection (compile-time) ----
    const __nv_bfloat16* A;
    const __nv_bfloat16* W;
    float* C;
    int K, N;
    if constexpr (TAG == 0) { A = g_tok;  W = g_win;  C = g_xz;   K = CCH;    N = 2 * DIN; }
    if constexpr (TAG == 1) { A = g_ubf;  W = g_wxp;  C = g_dbc;  K = DIN;    N = DBC_LD; }
    if constexpr (TAG == 2) { A = g_dtlo; W = g_wdt;  C = g_ddot; K = DTK_LD; N = DIN; }
    if constexpr (TAG == 3) { A = g_y;    W = g_wout; C = g_o;    K = DIN;    N = CCH; }

    __shared__ __nv_bfloat16 As[GBM * SROW];
    __shared__ __nv_bfloat16 Ws[GBN * SROW];
    const int tid  = threadIdx.x;
    const int lane = tid & 31, wid = tid >> 5;
    const int wm = wid & 1, wn = wid >> 1;
    const int m0 = blockIdx.y * GBM, n0 = blockIdx.x * GBN;
    const int gid = lane >> 2, tq = lane & 3;

    float acc[4][4][4];
    #pragma unroll
    for (int i = 0; i < 4; i++)
        #pragma unroll
        for (int j = 0; j < 4; j++)
            #pragma unroll
            for (int r = 0; r < 4; r++) acc[i][j][r] = 0.f;

    for (int k0 = 0; k0 < K; k0 += GBK) {
        #pragma unroll
        for (int i = 0; i < 2; i++) {
            int idx = tid + i * 256;
            int row = idx >> 2, seg = (idx & 3) * 8;
            *(uint4*)&As[row * SROW + seg] =
                *(const uint4*)&A[(size_t)(m0 + row) * K + k0 + seg];
            *(uint4*)&Ws[row * SROW + seg] =
                *(const uint4*)&W[(size_t)(n0 + row) * K + k0 + seg];
        }
        __syncthreads();
        #pragma unroll
        for (int kk = 0; kk < 2; kk++) {
            const int kb = kk * 16;
            uint32_t af[4][4], bfr[4][2];
            #pragma unroll
            for (int mf = 0; mf < 4; mf++) {
                int r = wm * 64 + mf * 16 + gid;
                af[mf][0] = lds32(&As[(r)     * SROW + kb + tq * 2]);
                af[mf][1] = lds32(&As[(r + 8) * SROW + kb + tq * 2]);
                af[mf][2] = lds32(&As[(r)     * SROW + kb + 8 + tq * 2]);
                af[mf][3] = lds32(&As[(r + 8) * SROW + kb + 8 + tq * 2]);
            }
            #pragma unroll
            for (int nf = 0; nf < 4; nf++) {
                int ncol = wn * 32 + nf * 8 + gid;
                bfr[nf][0] = lds32(&Ws[ncol * SROW + kb + tq * 2]);
                bfr[nf][1] = lds32(&Ws[ncol * SROW + kb + 8 + tq * 2]);
            }
            #pragma unroll
            for (int mf = 0; mf < 4; mf++)
                #pragma unroll
                for (int nf = 0; nf < 4; nf++)
                    mma16816(acc[mf][nf], af[mf], bfr[nf]);
        }
        __syncthreads();
    }
    #pragma unroll
    for (int mf = 0; mf < 4; mf++) {
        int m = m0 + wm * 64 + mf * 16 + gid;
        #pragma unroll
        for (int nf = 0; nf < 4; nf++) {
            int n = n0 + wn * 32 + nf * 8 + tq * 2;
            float* p = C + (size_t)m * N + n;
            p[0] = acc[mf][nf][0]; p[1] = acc[mf][nf][1];
            p += (size_t)8 * N;
            p[0] = acc[mf][nf][2]; p[1] = acc[mf][nf][3];
        }
    }
}

// ---------------------------------------------------------------------------
// Causal depthwise conv1d (width 4) + bias + SiLU.
// ---------------------------------------------------------------------------
__global__ void conv_silu_kernel(const float* __restrict__ cw,
                                 const float* __restrict__ cb) {
    int idx = blockIdx.x * 256 + threadIdx.x;     // grid covers MTOK*DIN exactly
    int d   = idx % DIN;
    int tok = idx / DIN;
    int l   = tok & (LSEQ - 1);
    float s = cb[d];
    const float* xp = g_xz + (size_t)tok * (2 * DIN) + d;
    #pragma unroll
    for (int k = 0; k < 4; k++) {
        int ls = l - 3 + k;
        if (ls >= 0) s += cw[d * 4 + k] * xp[(ptrdiff_t)(k - 3) * (2 * DIN)];
    }
    float sv = s / (1.0f + __expf(-s));
    g_u[idx]   = sv;
    g_ubf[idx] = __float2bfloat16(sv);
}

// ---------------------------------------------------------------------------
// dt_lo fp32 [M, padded dbc] -> bf16 [M,32] (cols 24..31 zero)
// ---------------------------------------------------------------------------
__global__ void dtlo_kernel() {
    int idx = blockIdx.x * 256 + threadIdx.x;     // MTOK*32 exact
    int k = idx & 31, tok = idx >> 5;
    g_dtlo[idx] = (k < 24) ? __float2bfloat16(g_dbc[(size_t)tok * DBC_LD + k])
                           : __float2bfloat16(0.f);
}

// ---------------------------------------------------------------------------
// Selective scan, fully fused:
//   dt = softplus(ddot + dt_proj_b);  h_n = h_n*exp(dt*A_n) + dt*u*B_n
//   y  = (sum_n h_n*C_n + u*D) * silu(z)
// 16-lane group = one (b,d) channel; lane n holds state n.
// ---------------------------------------------------------------------------
__global__ __launch_bounds__(256)
void scan_kernel(const float* __restrict__ A_log, const float* __restrict__ Dp,
                 const float* __restrict__ dtb) {
    const int tid = threadIdx.x;
    const int n   = tid & 15;
    const int g   = tid >> 4;
    const int d   = blockIdx.x * 16 + g;
    const int b   = blockIdx.y;
    const float An   = -__expf(A_log[d * DST + n]);
    const float Dd   = Dp[d];
    const float bias = dtb[d];
    float h = 0.f;
    const float* pd = g_ddot + (size_t)b * LSEQ * DIN + d;
    const float* pu = g_u    + (size_t)b * LSEQ * DIN + d;
    const float* pz = g_xz   + (size_t)b * LSEQ * (2 * DIN) + DIN + d;
    const float* pb = g_dbc  + (size_t)b * LSEQ * DBC_LD + 24 + n;
    __nv_bfloat16* py = g_y  + (size_t)b * LSEQ * DIN + d;

    for (int l = 0; l < LSEQ; l++) {
        float xr = *pd + bias;
        float dt = (xr > 15.f) ? xr : log1pf(__expf(xr));   // softplus
        float uu = *pu;
        float Bt = pb[0];
        float Ct = pb[DST];
        h = h * __expf(dt * An) + (dt * uu) * Bt;
        float p = h * Ct;
        p += __shfl_xor_sync(0xffffffffu, p, 8);
        p += __shfl_xor_sync(0xffffffffu, p, 4);
        p += __shfl_xor_sync(0xffffffffu, p, 2);
        p += __shfl_xor_sync(0xffffffffu, p, 1);
        if (n == 0) {
            float z = *pz;
            *py = __float2bfloat16((p + uu * Dd) * (z / (1.0f + __expf(-z))));
        }
        pd += DIN; pu += DIN; pz += 2 * DIN; pb += DBC_LD; py += DIN;
    }
}

// ---------------------------------------------------------------------------
// Epilogue: out[b,c,l] = g_o[b*L+l, c] + x[b,c,l]  (smem tile transpose)
// ---------------------------------------------------------------------------
__global__ __launch_bounds__(256)
void epilogue_kernel(const float* __restrict__ x, float* __restrict__ out) {
    __shared__ float t[32 * 33];
    const int b  = blockIdx.z;
    const int c0 = blockIdx.y * 32;
    const int l0 = blockIdx.x * 32;
    const int tid = threadIdx.x;
    #pragma unroll
    for (int i = 0; i < 4; i++) {
        int idx = tid + i * 256;
        int lr = idx >> 5, c = idx & 31;
        t[c * 33 + lr] = g_o[((size_t)b * LSEQ + l0 + lr) * CCH + c0 + c];
    }
    __syncthreads();
    #pragma unroll
    for (int i = 0; i < 4; i++) {
        int idx = tid + i * 256;
        int cr = idx >> 5, l = idx & 31;
        size_t oi = ((size_t)b * CCH + c0 + cr) * LSEQ + l0 + l;
        out[oi] = t[cr * 33 + l] + x[oi];
    }
}

// ---------------------------------------------------------------------------
// Launch — only d_in/d_out pointers cross the host/device boundary.
// ---------------------------------------------------------------------------
extern "C" void kernel_launch(void* const* d_in, const int* in_sizes, int n_in,
                              void* d_out, int out_size) {
    const float* x         = (const float*)d_in[0];
    const float* ln_w      = (const float*)d_in[1];
    const float* ln_b      = (const float*)d_in[2];
    const float* in_proj_w = (const float*)d_in[3];
    const float* conv_w    = (const float*)d_in[4];
    const float* conv_b    = (const float*)d_in[5];
    const float* x_proj_w  = (const float*)d_in[6];
    const float* dt_proj_w = (const float*)d_in[7];
    const float* dt_proj_b = (const float*)d_in[8];
    const float* A_log     = (const float*)d_in[9];
    const float* Dp        = (const float*)d_in[10];
    const float* out_proj_w= (const float*)d_in[11];
    float* out = (float*)d_out;
    (void)in_sizes; (void)n_in; (void)out_size;

    // 1. weights fp32 -> bf16 (padded)
    convert_weights<<<(2 * DIN * CCH + 255) / 256, 256>>>(in_proj_w, out_proj_w,
                                                          x_proj_w, dt_proj_w);
    // 2. LayerNorm -> bf16 tokens [M, 384]
    ln_kernel<<<dim3(LSEQ / 16, BATCH), 256>>>(x, ln_w, ln_b);
    // 3. in_proj: [8192,384] x [1536,384]^T -> g_xz
    gemm_tc<0><<<dim3(2 * DIN / GBN, MTOK / GBM), 256>>>();
    // 4. causal conv + SiLU -> g_u / g_ubf
    conv_silu_kernel<<<MTOK * DIN / 256, 256>>>(conv_w, conv_b);
    // 5. x_proj: [8192,768] x [128,768]^T -> g_dbc (padded N)
    gemm_tc<1><<<dim3(DBC_LD / GBN, MTOK / GBM), 256>>>();
    // 6. dt_lo -> bf16 padded [M,32]
    dtlo_kernel<<<MTOK * DTK_LD / 256, 256>>>();
    // 7. dt_proj: [8192,32] x [768,32]^T -> g_ddot
    gemm_tc<2><<<dim3(DIN / GBN, MTOK / GBM), 256>>>();
    // 8. fused selective scan + softplus + D-skip + SiLU gate -> g_y
    scan_kernel<<<dim3(DIN / 16, BATCH), 256>>>(A_log, Dp, dt_proj_b);
    // 9. out_proj: [8192,768] x [384,768]^T -> g_o
    gemm_tc<3><<<dim3(CCH / GBN, MTOK / GBM), 256>>>();
    // 10. transpose + residual -> out [B,C,H,W]
    epilogue_kernel<<<dim3(LSEQ / 32, CCH / 32, BATCH), 256>>>(x, out);
}

// round 10
// speedup vs baseline: 3.3341x; 3.3341x over previous
#include <cuda_runtime.h>
#include <cuda_bf16.h>
#include <cstdint>
#include <cstddef>

// ---------------------------------------------------------------------------
// Problem constants
// ---------------------------------------------------------------------------
static constexpr int BATCH   = 8;
static constexpr int CCH     = 384;
static constexpr int LSEQ    = 1024;
static constexpr int MTOK    = BATCH * LSEQ;       // 8192
static constexpr int DIN     = 768;
static constexpr int DST     = 16;
static constexpr int DBC_LD  = 128;                // padded x_proj output stride
static constexpr int DTK_LD  = 32;                 // padded dt_rank
static constexpr int NCH     = 8;                  // scan chunks
static constexpr int CLEN    = LSEQ / NCH;         // 128

// ---------------------------------------------------------------------------
// Scratch (device globals; all access from device code only)
// ---------------------------------------------------------------------------
__device__ __align__(16) float          g_xz  [MTOK * 2 * DIN];
__device__ __align__(16) float          g_u   [MTOK * DIN];
__device__ __align__(16) __nv_bfloat16  g_ubf [MTOK * DIN];
__device__ __align__(16) __nv_bfloat16  g_tok [MTOK * CCH];
__device__ __align__(16) float          g_dbc [MTOK * DBC_LD];
__device__ __align__(16) __nv_bfloat16  g_dtlo[MTOK * DTK_LD];
__device__ __align__(16) float          g_ddot[MTOK * DIN];
__device__ __align__(16) float          g_dt  [MTOK * DIN];
__device__ __align__(16) __nv_bfloat16  g_y   [MTOK * DIN];
__device__ __align__(16) float          g_o   [MTOK * CCH];
__device__ __align__(16) float          g_hout[BATCH * NCH * DIN * DST];
__device__ __align__(16) float          g_hin [BATCH * NCH * DIN * DST];
__device__ __align__(16) float          g_sdt [BATCH * NCH * DIN];
__device__ __align__(16) __nv_bfloat16  g_win [2 * DIN * CCH];
__device__ __align__(16) __nv_bfloat16  g_wout[CCH * DIN];
__device__ __align__(16) __nv_bfloat16  g_wxp [DBC_LD * DIN];
__device__ __align__(16) __nv_bfloat16  g_wdt [DIN * DTK_LD];

// ---------------------------------------------------------------------------
// Weight conversion fp32 -> bf16 (with zero padding)
// ---------------------------------------------------------------------------
__global__ void convert_weights(const float* __restrict__ win,
                                const float* __restrict__ wout,
                                const float* __restrict__ wxp,
                                const float* __restrict__ wdt) {
    int i = blockIdx.x * 256 + threadIdx.x;
    if (i < 2 * DIN * CCH) g_win[i] = __float2bfloat16(win[i]);
    if (i < CCH * DIN)     g_wout[i] = __float2bfloat16(wout[i]);
    if (i < DBC_LD * DIN)  g_wxp[i] = (i < 56 * DIN) ? __float2bfloat16(wxp[i])
                                                     : __float2bfloat16(0.f);
    if (i < DIN * DTK_LD) {
        int r = i >> 5, c = i & 31;
        g_wdt[i] = (c < 24) ? __float2bfloat16(wdt[r * 24 + c]) : __float2bfloat16(0.f);
    }
}

// ---------------------------------------------------------------------------
// LayerNorm over channels + transpose to token-major bf16
// ---------------------------------------------------------------------------
__global__ __launch_bounds__(256)
void ln_kernel(const float* __restrict__ x, const float* __restrict__ lnw,
               const float* __restrict__ lnb) {
    __shared__ float xs[CCH * 17];
    __shared__ float ps[16 * 16], pq[16 * 16];
    __shared__ float mu_s[16], rs_s[16];
    const int b  = blockIdx.y;
    const int l0 = blockIdx.x * 16;
    const int tid = threadIdx.x;

    for (int idx = tid; idx < CCH * 16; idx += 256) {
        int c = idx >> 4, l = idx & 15;
        xs[c * 17 + l] = x[((size_t)b * CCH + c) * LSEQ + l0 + l];
    }
    __syncthreads();
    {
        int l = tid & 15, g = tid >> 4;
        float s = 0.f, q = 0.f;
        for (int c = g; c < CCH; c += 16) {
            float v = xs[c * 17 + l];
            s += v; q += v * v;
        }
        ps[g * 16 + l] = s; pq[g * 16 + l] = q;
    }
    __syncthreads();
    if (tid < 16) {
        float s = 0.f, q = 0.f;
        #pragma unroll
        for (int g = 0; g < 16; g++) { s += ps[g * 16 + tid]; q += pq[g * 16 + tid]; }
        float mu  = s * (1.0f / CCH);
        float var = q * (1.0f / CCH) - mu * mu;
        mu_s[tid] = mu;
        rs_s[tid] = rsqrtf(var + 1e-5f);
    }
    __syncthreads();
    for (int idx = tid; idx < CCH * 16; idx += 256) {
        int c = idx % CCH, l = idx / CCH;
        float v = (xs[c * 17 + l] - mu_s[l]) * rs_s[l] * lnw[c] + lnb[c];
        g_tok[((size_t)b * LSEQ + l0 + l) * CCH + c] = __float2bfloat16(v);
    }
}

// ---------------------------------------------------------------------------
// bf16 tensor-core GEMM with 2-stage cp.async double buffering.
//   TAG 0: g_tok  x g_win  -> g_xz    (K=384, N=1536)
//   TAG 1: g_ubf  x g_wxp  -> g_dbc   (K=768, N=128)
//   TAG 2: g_dtlo x g_wdt  -> g_ddot  (K=32,  N=768)
//   TAG 3: g_y    x g_wout -> g_o     (K=768, N=384)
// ---------------------------------------------------------------------------
__device__ __forceinline__ uint32_t lds32(const __nv_bfloat16* p) {
    return *reinterpret_cast<const uint32_t*>(p);
}
__device__ __forceinline__ void mma16816(float* d, const uint32_t* a, const uint32_t* b) {
    asm volatile(
        "mma.sync.aligned.m16n8k16.row.col.f32.bf16.bf16.f32 "
        "{%0,%1,%2,%3}, {%4,%5,%6,%7}, {%8,%9}, {%0,%1,%2,%3};\n"
        : "+f"(d[0]), "+f"(d[1]), "+f"(d[2]), "+f"(d[3])
        : "r"(a[0]), "r"(a[1]), "r"(a[2]), "r"(a[3]), "r"(b[0]), "r"(b[1]));
}
__device__ __forceinline__ void cp_async16(uint32_t dst, const void* src) {
    asm volatile("cp.async.cg.shared.global [%0], [%1], 16;\n" :: "r"(dst), "l"(src));
}

static constexpr int GBM = 128, GBN = 128, GBK = 32;
static constexpr int SROW = GBK + 8;   // smem row stride (bf16) -> conflict-free

template<int TAG>
__global__ __launch_bounds__(256) void gemm_tc() {
    const __nv_bfloat16* A;
    const __nv_bfloat16* W;
    float* C;
    int K, N;
    if constexpr (TAG == 0) { A = g_tok;  W = g_win;  C = g_xz;   K = CCH;    N = 2 * DIN; }
    if constexpr (TAG == 1) { A = g_ubf;  W = g_wxp;  C = g_dbc;  K = DIN;    N = DBC_LD; }
    if constexpr (TAG == 2) { A = g_dtlo; W = g_wdt;  C = g_ddot; K = DTK_LD; N = DIN; }
    if constexpr (TAG == 3) { A = g_y;    W = g_wout; C = g_o;    K = DIN;    N = CCH; }

    __shared__ __nv_bfloat16 As[2][GBM * SROW];
    __shared__ __nv_bfloat16 Ws[2][GBN * SROW];
    const int tid  = threadIdx.x;
    const int lane = tid & 31, wid = tid >> 5;
    const int wm = wid & 1, wn = wid >> 1;
    const int m0 = blockIdx.y * GBM, n0 = blockIdx.x * GBN;
    const int gid = lane >> 2, tq = lane & 3;

    // per-thread staging coordinates (two 16B segments)
    const int r0 = tid >> 2, s0 = (tid & 3) * 8;
    const int r1 = (tid + 256) >> 2, s1 = ((tid + 256) & 3) * 8;

    float acc[4][4][4];
    #pragma unroll
    for (int i = 0; i < 4; i++)
        #pragma unroll
        for (int j = 0; j < 4; j++)
            #pragma unroll
            for (int r = 0; r < 4; r++) acc[i][j][r] = 0.f;

    const int nk = K / GBK;
    auto issue_stage = [&](int ki, int st) {
        int k0 = ki * GBK;
        cp_async16((uint32_t)__cvta_generic_to_shared(&As[st][r0 * SROW + s0]),
                   &A[(size_t)(m0 + r0) * K + k0 + s0]);
        cp_async16((uint32_t)__cvta_generic_to_shared(&As[st][r1 * SROW + s1]),
                   &A[(size_t)(m0 + r1) * K + k0 + s1]);
        cp_async16((uint32_t)__cvta_generic_to_shared(&Ws[st][r0 * SROW + s0]),
                   &W[(size_t)(n0 + r0) * K + k0 + s0]);
        cp_async16((uint32_t)__cvta_generic_to_shared(&Ws[st][r1 * SROW + s1]),
                   &W[(size_t)(n0 + r1) * K + k0 + s1]);
        asm volatile("cp.async.commit_group;\n");
    };

    issue_stage(0, 0);
    for (int ki = 0; ki < nk; ki++) {
        asm volatile("cp.async.wait_group 0;\n");
        __syncthreads();
        if (ki + 1 < nk) issue_stage(ki + 1, (ki + 1) & 1);
        const __nv_bfloat16* Ab = As[ki & 1];
        const __nv_bfloat16* Wb = Ws[ki & 1];
        #pragma unroll
        for (int kk = 0; kk < 2; kk++) {
            const int kb = kk * 16;
            uint32_t af[4][4], bfr[4][2];
            #pragma unroll
            for (int mf = 0; mf < 4; mf++) {
                int r = wm * 64 + mf * 16 + gid;
                af[mf][0] = lds32(&Ab[(r)     * SROW + kb + tq * 2]);
                af[mf][1] = lds32(&Ab[(r + 8) * SROW + kb + tq * 2]);
                af[mf][2] = lds32(&Ab[(r)     * SROW + kb + 8 + tq * 2]);
                af[mf][3] = lds32(&Ab[(r + 8) * SROW + kb + 8 + tq * 2]);
            }
            #pragma unroll
            for (int nf = 0; nf < 4; nf++) {
                int ncol = wn * 32 + nf * 8 + gid;
                bfr[nf][0] = lds32(&Wb[ncol * SROW + kb + tq * 2]);
                bfr[nf][1] = lds32(&Wb[ncol * SROW + kb + 8 + tq * 2]);
            }
            #pragma unroll
            for (int mf = 0; mf < 4; mf++)
                #pragma unroll
                for (int nf = 0; nf < 4; nf++)
                    mma16816(acc[mf][nf], af[mf], bfr[nf]);
        }
        __syncthreads();
    }
    #pragma unroll
    for (int mf = 0; mf < 4; mf++) {
        int m = m0 + wm * 64 + mf * 16 + gid;
        #pragma unroll
        for (int nf = 0; nf < 4; nf++) {
            int n = n0 + wn * 32 + nf * 8 + tq * 2;
            float* p = C + (size_t)m * N + n;
            p[0] = acc[mf][nf][0]; p[1] = acc[mf][nf][1];
            p += (size_t)8 * N;
            p[0] = acc[mf][nf][2]; p[1] = acc[mf][nf][3];
        }
    }
}

// ---------------------------------------------------------------------------
// Causal depthwise conv1d (width 4) + bias + SiLU
// ---------------------------------------------------------------------------
__global__ void conv_silu_kernel(const float* __restrict__ cw,
                                 const float* __restrict__ cb) {
    int idx = blockIdx.x * 256 + threadIdx.x;
    int d   = idx % DIN;
    int tok = idx / DIN;
    int l   = tok & (LSEQ - 1);
    float s = cb[d];
    const float* xp = g_xz + (size_t)tok * (2 * DIN) + d;
    #pragma unroll
    for (int k = 0; k < 4; k++) {
        int ls = l - 3 + k;
        if (ls >= 0) s += cw[d * 4 + k] * xp[(ptrdiff_t)(k - 3) * (2 * DIN)];
    }
    float sv = s / (1.0f + __expf(-s));
    g_u[idx]   = sv;
    g_ubf[idx] = __float2bfloat16(sv);
}

// ---------------------------------------------------------------------------
// dt_lo fp32 -> bf16 padded [M,32]
// ---------------------------------------------------------------------------
__global__ void dtlo_kernel() {
    int idx = blockIdx.x * 256 + threadIdx.x;
    int k = idx & 31, tok = idx >> 5;
    g_dtlo[idx] = (k < 24) ? __float2bfloat16(g_dbc[(size_t)tok * DBC_LD + k])
                           : __float2bfloat16(0.f);
}

// ---------------------------------------------------------------------------
// dt = softplus(ddot + dt_proj_b)  (parallel, computed once)
// ---------------------------------------------------------------------------
__global__ void dt_kernel(const float* __restrict__ dtb) {
    int idx = blockIdx.x * 256 + threadIdx.x;      // MTOK*DIN exact
    int d   = idx % DIN;
    float xr = g_ddot[idx] + dtb[d];
    g_dt[idx] = (xr > 15.f) ? xr : log1pf(__expf(xr));
}

// ---------------------------------------------------------------------------
// Scan pass 1: per-chunk local scan (h0=0) -> h_out, sum_dt.
// Block: 256 thr = 16 channel-groups x 16 states. Grid (DIN/16, NCH, B).
// All chunk data staged in smem (coalesced) so the loop runs from LDS.
// ---------------------------------------------------------------------------
__global__ __launch_bounds__(256)
void scan_pass1(const float* __restrict__ A_log) {
    __shared__ float sdt[CLEN * 16], su[CLEN * 16], sB[CLEN * 16];
    const int tid = threadIdx.x;
    const int n = tid & 15, g = tid >> 4;
    const int d0 = blockIdx.x * 16, c = blockIdx.y, b = blockIdx.z;
    const size_t tokbase = (size_t)b * LSEQ + c * CLEN;

    for (int idx = tid; idx < CLEN * 16; idx += 256) {
        int l = idx >> 4, dd = idx & 15;
        size_t row = tokbase + l;
        sdt[idx] = g_dt[row * DIN + d0 + dd];
        su[idx]  = g_u [row * DIN + d0 + dd];
        sB[idx]  = g_dbc[row * DBC_LD + 24 + dd];
    }
    __syncthreads();

    const int d = d0 + g;
    const float An = -__expf(A_log[d * DST + n]);
    float h = 0.f, sum = 0.f;
    #pragma unroll 4
    for (int l = 0; l < CLEN; l++) {
        float dt = sdt[l * 16 + g];
        float uu = su[l * 16 + g];
        float B  = sB[l * 16 + n];
        h = h * __expf(dt * An) + (dt * uu) * B;
        sum += dt;
    }
    size_t idxc = ((size_t)(b * NCH + c) * DIN + d);
    g_hout[idxc * DST + n] = h;
    if (n == 0) g_sdt[idxc] = sum;
}

// ---------------------------------------------------------------------------
// Scan pass 2: propagate chunk-boundary states (8 sequential steps/thread).
// chunk product of exp(dt*An) = exp(An * sum_dt).
// ---------------------------------------------------------------------------
__global__ __launch_bounds__(256)
void scan_pass2(const float* __restrict__ A_log) {
    int t = blockIdx.x * 256 + threadIdx.x;        // B*DIN*16 exact
    int n = t & 15;
    int d = (t >> 4) % DIN;
    int b = t / (DIN * DST);
    const float An = -__expf(A_log[d * DST + n]);
    float hin = 0.f;
    #pragma unroll
    for (int c = 0; c < NCH; c++) {
        size_t idxc = ((size_t)(b * NCH + c) * DIN + d);
        g_hin[idxc * DST + n] = hin;
        hin = g_hout[idxc * DST + n] + __expf(An * g_sdt[idxc]) * hin;
    }
}

// ---------------------------------------------------------------------------
// Scan pass 3: full per-chunk scan with correct h0; fused y-reduction,
// D-skip, SiLU gate; cooperative bf16 writeout.
// ---------------------------------------------------------------------------
__global__ __launch_bounds__(256)
void scan_pass3(const float* __restrict__ A_log, const float* __restrict__ Dp) {
    __shared__ float sdt[CLEN * 16], su[CLEN * 16], sB[CLEN * 16],
                     sC[CLEN * 16], sy[CLEN * 16];
    const int tid = threadIdx.x;
    const int n = tid & 15, g = tid >> 4;
    const int d0 = blockIdx.x * 16, c = blockIdx.y, b = blockIdx.z;
    const size_t tokbase = (size_t)b * LSEQ + c * CLEN;

    for (int idx = tid; idx < CLEN * 16; idx += 256) {
        int l = idx >> 4, dd = idx & 15;
        size_t row = tokbase + l;
        sdt[idx] = g_dt[row * DIN + d0 + dd];
        su[idx]  = g_u [row * DIN + d0 + dd];
        sB[idx]  = g_dbc[row * DBC_LD + 24 + dd];
        sC[idx]  = g_dbc[row * DBC_LD + 24 + DST + dd];
    }
    __syncthreads();

    const int d = d0 + g;
    const float An = -__expf(A_log[d * DST + n]);
    const float Dd = Dp[d];
    size_t idxc = ((size_t)(b * NCH + c) * DIN + d);
    float h = g_hin[idxc * DST + n];

    for (int l = 0; l < CLEN; l++) {
        float dt = sdt[l * 16 + g];
        float uu = su[l * 16 + g];
        float B  = sB[l * 16 + n];
        float Ct = sC[l * 16 + n];
        h = h * __expf(dt * An) + (dt * uu) * B;
        float p = h * Ct;
        p += __shfl_xor_sync(0xffffffffu, p, 8);
        p += __shfl_xor_sync(0xffffffffu, p, 4);
        p += __shfl_xor_sync(0xffffffffu, p, 2);
        p += __shfl_xor_sync(0xffffffffu, p, 1);
        if (n == 0) sy[l * 16 + g] = p + uu * Dd;
    }
    __syncthreads();

    for (int idx = tid; idx < CLEN * 16; idx += 256) {
        int l = idx >> 4, dd = idx & 15;
        size_t row = tokbase + l;
        float z = g_xz[row * (2 * DIN) + DIN + d0 + dd];
        float y = sy[idx] * (z / (1.0f + __expf(-z)));
        g_y[row * DIN + d0 + dd] = __float2bfloat16(y);
    }
}

// ---------------------------------------------------------------------------
// Epilogue: out[b,c,l] = g_o[b*L+l, c] + x[b,c,l]
// ---------------------------------------------------------------------------
__global__ __launch_bounds__(256)
void epilogue_kernel(const float* __restrict__ x, float* __restrict__ out) {
    __shared__ float t[32 * 33];
    const int b  = blockIdx.z;
    const int c0 = blockIdx.y * 32;
    const int l0 = blockIdx.x * 32;
    const int tid = threadIdx.x;
    #pragma unroll
    for (int i = 0; i < 4; i++) {
        int idx = tid + i * 256;
        int lr = idx >> 5, c = idx & 31;
        t[c * 33 + lr] = g_o[((size_t)b * LSEQ + l0 + lr) * CCH + c0 + c];
    }
    __syncthreads();
    #pragma unroll
    for (int i = 0; i < 4; i++) {
        int idx = tid + i * 256;
        int cr = idx >> 5, l = idx & 31;
        size_t oi = ((size_t)b * CCH + c0 + cr) * LSEQ + l0 + l;
        out[oi] = t[cr * 33 + l] + x[oi];
    }
}

// ---------------------------------------------------------------------------
// Launch
// ---------------------------------------------------------------------------
extern "C" void kernel_launch(void* const* d_in, const int* in_sizes, int n_in,
                              void* d_out, int out_size) {
    const float* x         = (const float*)d_in[0];
    const float* ln_w      = (const float*)d_in[1];
    const float* ln_b      = (const float*)d_in[2];
    const float* in_proj_w = (const float*)d_in[3];
    const float* conv_w    = (const float*)d_in[4];
    const float* conv_b    = (const float*)d_in[5];
    const float* x_proj_w  = (const float*)d_in[6];
    const float* dt_proj_w = (const float*)d_in[7];
    const float* dt_proj_b = (const float*)d_in[8];
    const float* A_log     = (const float*)d_in[9];
    const float* Dp        = (const float*)d_in[10];
    const float* out_proj_w= (const float*)d_in[11];
    float* out = (float*)d_out;
    (void)in_sizes; (void)n_in; (void)out_size;

    convert_weights<<<(2 * DIN * CCH + 255) / 256, 256>>>(in_proj_w, out_proj_w,
                                                          x_proj_w, dt_proj_w);
    ln_kernel<<<dim3(LSEQ / 16, BATCH), 256>>>(x, ln_w, ln_b);
    gemm_tc<0><<<dim3(2 * DIN / GBN, MTOK / GBM), 256>>>();
    conv_silu_kernel<<<MTOK * DIN / 256, 256>>>(conv_w, conv_b);
    gemm_tc<1><<<dim3(DBC_LD / GBN, MTOK / GBM), 256>>>();
    dtlo_kernel<<<MTOK * DTK_LD / 256, 256>>>();
    gemm_tc<2><<<dim3(DIN / GBN, MTOK / GBM), 256>>>();
    dt_kernel<<<MTOK * DIN / 256, 256>>>(dt_proj_b);
    scan_pass1<<<dim3(DIN / 16, NCH, BATCH), 256>>>(A_log);
    scan_pass2<<<BATCH * DIN * DST / 256, 256>>>(A_log);
    scan_pass3<<<dim3(DIN / 16, NCH, BATCH), 256>>>(A_log, Dp);
    gemm_tc<3><<<dim3(CCH / GBN, MTOK / GBM), 256>>>();
    epilogue_kernel<<<dim3(LSEQ / 32, CCH / 32, BATCH), 256>>>(x, out);
}

// round 12
// speedup vs baseline: 3.6543x; 1.0961x over previous
#include <cuda_runtime.h>
#include <cuda_bf16.h>
#include <cstdint>
#include <cstddef>

// ---------------------------------------------------------------------------
// Problem constants
// ---------------------------------------------------------------------------
static constexpr int BATCH   = 8;
static constexpr int CCH     = 384;
static constexpr int LSEQ    = 1024;
static constexpr int MTOK    = BATCH * LSEQ;       // 8192
static constexpr int DIN     = 768;
static constexpr int DST     = 16;
static constexpr int DBC_LD  = 128;                // padded x_proj output stride
static constexpr int DTK_LD  = 32;                 // padded dt_rank
static constexpr int NCH     = 8;                  // scan chunks
static constexpr int CLEN    = LSEQ / NCH;         // 128

// ---------------------------------------------------------------------------
// Scratch (device globals; all access from device code only)
// ---------------------------------------------------------------------------
__device__ __align__(16) __nv_bfloat16  g_xzb [MTOK * 2 * DIN];  // in_proj out bf16 (x|z)
__device__ __align__(16) __nv_bfloat16  g_ubf [MTOK * DIN];      // conv+silu bf16
__device__ __align__(16) __nv_bfloat16  g_tok [MTOK * CCH];      // LN tokens bf16
__device__ __align__(16) float          g_dbc [MTOK * DBC_LD];   // x_proj out fp32 (B,C cols)
__device__ __align__(16) __nv_bfloat16  g_dtlo[MTOK * DTK_LD];   // dt_lo bf16 (from TAG1 epi)
__device__ __align__(16) __nv_bfloat16  g_dtb [MTOK * DIN];      // dt = softplus(...) bf16
__device__ __align__(16) __nv_bfloat16  g_y   [MTOK * DIN];      // gated scan output bf16
__device__ __align__(16) __nv_bfloat16  g_ob  [MTOK * CCH];      // out_proj out bf16
__device__ __align__(16) float          g_hout[BATCH * NCH * DIN * DST];
__device__ __align__(16) float          g_sdt [BATCH * NCH * DIN];
__device__ __align__(16) __nv_bfloat16  g_win [2 * DIN * CCH];
__device__ __align__(16) __nv_bfloat16  g_wout[CCH * DIN];
__device__ __align__(16) __nv_bfloat16  g_wxp [DBC_LD * DIN];
__device__ __align__(16) __nv_bfloat16  g_wdt [DIN * DTK_LD];

__device__ __forceinline__ float softplusf(float x) {
    return (x > 15.f) ? x : log1pf(__expf(x));
}
__device__ __forceinline__ void store_bf2(__nv_bfloat16* p, size_t i, float a, float b) {
    __nv_bfloat162 v;
    v.x = __float2bfloat16(a);
    v.y = __float2bfloat16(b);
    *reinterpret_cast<__nv_bfloat162*>(p + i) = v;
}

// ---------------------------------------------------------------------------
// Weight conversion fp32 -> bf16 (with zero padding)
// ---------------------------------------------------------------------------
__global__ void convert_weights(const float* __restrict__ win,
                                const float* __restrict__ wout,
                                const float* __restrict__ wxp,
                                const float* __restrict__ wdt) {
    int i = blockIdx.x * 256 + threadIdx.x;
    if (i < 2 * DIN * CCH) g_win[i] = __float2bfloat16(win[i]);
    if (i < CCH * DIN)     g_wout[i] = __float2bfloat16(wout[i]);
    if (i < DBC_LD * DIN)  g_wxp[i] = (i < 56 * DIN) ? __float2bfloat16(wxp[i])
                                                     : __float2bfloat16(0.f);
    if (i < DIN * DTK_LD) {
        int r = i >> 5, c = i & 31;
        g_wdt[i] = (c < 24) ? __float2bfloat16(wdt[r * 24 + c]) : __float2bfloat16(0.f);
    }
}

// ---------------------------------------------------------------------------
// LayerNorm over channels + transpose to token-major bf16
// ---------------------------------------------------------------------------
__global__ __launch_bounds__(256)
void ln_kernel(const float* __restrict__ x, const float* __restrict__ lnw,
               const float* __restrict__ lnb) {
    __shared__ float xs[CCH * 17];
    __shared__ float ps[16 * 16], pq[16 * 16];
    __shared__ float mu_s[16], rs_s[16];
    const int b  = blockIdx.y;
    const int l0 = blockIdx.x * 16;
    const int tid = threadIdx.x;

    for (int idx = tid; idx < CCH * 16; idx += 256) {
        int c = idx >> 4, l = idx & 15;
        xs[c * 17 + l] = x[((size_t)b * CCH + c) * LSEQ + l0 + l];
    }
    __syncthreads();
    {
        int l = tid & 15, g = tid >> 4;
        float s = 0.f, q = 0.f;
        for (int c = g; c < CCH; c += 16) {
            float v = xs[c * 17 + l];
            s += v; q += v * v;
        }
        ps[g * 16 + l] = s; pq[g * 16 + l] = q;
    }
    __syncthreads();
    if (tid < 16) {
        float s = 0.f, q = 0.f;
        #pragma unroll
        for (int g = 0; g < 16; g++) { s += ps[g * 16 + tid]; q += pq[g * 16 + tid]; }
        float mu  = s * (1.0f / CCH);
        float var = q * (1.0f / CCH) - mu * mu;
        mu_s[tid] = mu;
        rs_s[tid] = rsqrtf(var + 1e-5f);
    }
    __syncthreads();
    for (int idx = tid; idx < CCH * 16; idx += 256) {
        int c = idx % CCH, l = idx / CCH;
        float v = (xs[c * 17 + l] - mu_s[l]) * rs_s[l] * lnw[c] + lnb[c];
        g_tok[((size_t)b * LSEQ + l0 + l) * CCH + c] = __float2bfloat16(v);
    }
}

// ---------------------------------------------------------------------------
// bf16 tensor-core GEMM with 2-stage cp.async double buffering + fused
// per-TAG epilogues:
//   TAG 0: g_tok  x g_win  -> g_xzb bf16              (K=384, N=1536)
//   TAG 1: g_ubf  x g_wxp  -> g_dbc fp32 + g_dtlo bf16 (K=768, N=128)
//   TAG 2: g_dtlo x g_wdt  -> g_dtb = softplus(+bias) bf16 (K=32, N=768)
//   TAG 3: g_y    x g_wout -> g_ob bf16               (K=768, N=384)
// ---------------------------------------------------------------------------
__device__ __forceinline__ uint32_t lds32(const __nv_bfloat16* p) {
    return *reinterpret_cast<const uint32_t*>(p);
}
__device__ __forceinline__ void mma16816(float* d, const uint32_t* a, const uint32_t* b) {
    asm volatile(
        "mma.sync.aligned.m16n8k16.row.col.f32.bf16.bf16.f32 "
        "{%0,%1,%2,%3}, {%4,%5,%6,%7}, {%8,%9}, {%0,%1,%2,%3};\n"
        : "+f"(d[0]), "+f"(d[1]), "+f"(d[2]), "+f"(d[3])
        : "r"(a[0]), "r"(a[1]), "r"(a[2]), "r"(a[3]), "r"(b[0]), "r"(b[1]));
}
__device__ __forceinline__ void cp_async16(uint32_t dst, const void* src) {
    asm volatile("cp.async.cg.shared.global [%0], [%1], 16;\n" :: "r"(dst), "l"(src));
}

static constexpr int GBM = 128, GBN = 128, GBK = 32;
static constexpr int SROW = GBK + 8;   // smem row stride (bf16) -> conflict-free

template<int TAG>
__global__ __launch_bounds__(256) void gemm_tc(const float* __restrict__ aux) {
    const __nv_bfloat16* A;
    const __nv_bfloat16* W;
    int K, N;
    if constexpr (TAG == 0) { A = g_tok;  W = g_win;  K = CCH;    N = 2 * DIN; }
    if constexpr (TAG == 1) { A = g_ubf;  W = g_wxp;  K = DIN;    N = DBC_LD; }
    if constexpr (TAG == 2) { A = g_dtlo; W = g_wdt;  K = DTK_LD; N = DIN; }
    if constexpr (TAG == 3) { A = g_y;    W = g_wout; K = DIN;    N = CCH; }

    __shared__ __nv_bfloat16 As[2][GBM * SROW];
    __shared__ __nv_bfloat16 Ws[2][GBN * SROW];
    const int tid  = threadIdx.x;
    const int lane = tid & 31, wid = tid >> 5;
    const int wm = wid & 1, wn = wid >> 1;
    const int m0 = blockIdx.y * GBM, n0 = blockIdx.x * GBN;
    const int gid = lane >> 2, tq = lane & 3;

    const int r0 = tid >> 2, s0 = (tid & 3) * 8;
    const int r1 = (tid + 256) >> 2, s1 = ((tid + 256) & 3) * 8;

    float acc[4][4][4];
    #pragma unroll
    for (int i = 0; i < 4; i++)
        #pragma unroll
        for (int j = 0; j < 4; j++)
            #pragma unroll
            for (int r = 0; r < 4; r++) acc[i][j][r] = 0.f;

    const int nk = K / GBK;
    auto issue_stage = [&](int ki, int st) {
        int k0 = ki * GBK;
        cp_async16((uint32_t)__cvta_generic_to_shared(&As[st][r0 * SROW + s0]),
                   &A[(size_t)(m0 + r0) * K + k0 + s0]);
        cp_async16((uint32_t)__cvta_generic_to_shared(&As[st][r1 * SROW + s1]),
                   &A[(size_t)(m0 + r1) * K + k0 + s1]);
        cp_async16((uint32_t)__cvta_generic_to_shared(&Ws[st][r0 * SROW + s0]),
                   &W[(size_t)(n0 + r0) * K + k0 + s0]);
        cp_async16((uint32_t)__cvta_generic_to_shared(&Ws[st][r1 * SROW + s1]),
                   &W[(size_t)(n0 + r1) * K + k0 + s1]);
        asm volatile("cp.async.commit_group;\n");
    };

    issue_stage(0, 0);
    for (int ki = 0; ki < nk; ki++) {
        asm volatile("cp.async.wait_group 0;\n");
        __syncthreads();
        if (ki + 1 < nk) issue_stage(ki + 1, (ki + 1) & 1);
        const __nv_bfloat16* Ab = As[ki & 1];
        const __nv_bfloat16* Wb = Ws[ki & 1];
        #pragma unroll
        for (int kk = 0; kk < 2; kk++) {
            const int kb = kk * 16;
            uint32_t af[4][4], bfr[4][2];
            #pragma unroll
            for (int mf = 0; mf < 4; mf++) {
                int r = wm * 64 + mf * 16 + gid;
                af[mf][0] = lds32(&Ab[(r)     * SROW + kb + tq * 2]);
                af[mf][1] = lds32(&Ab[(r + 8) * SROW + kb + tq * 2]);
                af[mf][2] = lds32(&Ab[(r)     * SROW + kb + 8 + tq * 2]);
                af[mf][3] = lds32(&Ab[(r + 8) * SROW + kb + 8 + tq * 2]);
            }
            #pragma unroll
            for (int nf = 0; nf < 4; nf++) {
                int ncol = wn * 32 + nf * 8 + gid;
                bfr[nf][0] = lds32(&Wb[ncol * SROW + kb + tq * 2]);
                bfr[nf][1] = lds32(&Wb[ncol * SROW + kb + 8 + tq * 2]);
            }
            #pragma unroll
            for (int mf = 0; mf < 4; mf++)
                #pragma unroll
                for (int nf = 0; nf < 4; nf++)
                    mma16816(acc[mf][nf], af[mf], bfr[nf]);
        }
        __syncthreads();
    }

    // ---- fused per-TAG epilogue ----
    #pragma unroll
    for (int mf = 0; mf < 4; mf++) {
        int m = m0 + wm * 64 + mf * 16 + gid;
        #pragma unroll
        for (int nf = 0; nf < 4; nf++) {
            int n = n0 + wn * 32 + nf * 8 + tq * 2;
            float v0 = acc[mf][nf][0], v1 = acc[mf][nf][1];
            float v2 = acc[mf][nf][2], v3 = acc[mf][nf][3];
            if constexpr (TAG == 0) {
                store_bf2(g_xzb, (size_t)m * N + n, v0, v1);
                store_bf2(g_xzb, (size_t)(m + 8) * N + n, v2, v3);
            } else if constexpr (TAG == 1) {
                g_dbc[(size_t)m * N + n]           = v0;
                g_dbc[(size_t)m * N + n + 1]       = v1;
                g_dbc[(size_t)(m + 8) * N + n]     = v2;
                g_dbc[(size_t)(m + 8) * N + n + 1] = v3;
                if (n < DTK_LD) {   // cols 24..31 multiply zero wdt cols -> no zeroing needed
                    store_bf2(g_dtlo, (size_t)m * DTK_LD + n, v0, v1);
                    store_bf2(g_dtlo, (size_t)(m + 8) * DTK_LD + n, v2, v3);
                }
            } else if constexpr (TAG == 2) {
                float b0 = aux[n], b1 = aux[n + 1];
                store_bf2(g_dtb, (size_t)m * N + n,
                          softplusf(v0 + b0), softplusf(v1 + b1));
                store_bf2(g_dtb, (size_t)(m + 8) * N + n,
                          softplusf(v2 + b0), softplusf(v3 + b1));
            } else {
                store_bf2(g_ob, (size_t)m * N + n, v0, v1);
                store_bf2(g_ob, (size_t)(m + 8) * N + n, v2, v3);
            }
        }
    }
}

// ---------------------------------------------------------------------------
// Causal depthwise conv1d (width 4) + bias + SiLU; bf16 in, bf16 out.
// ---------------------------------------------------------------------------
__global__ void conv_silu_kernel(const float* __restrict__ cw,
                                 const float* __restrict__ cb) {
    int idx = blockIdx.x * 256 + threadIdx.x;
    int d   = idx % DIN;
    int tok = idx / DIN;
    int l   = tok & (LSEQ - 1);
    float s = cb[d];
    const __nv_bfloat16* xp = g_xzb + (size_t)tok * (2 * DIN) + d;
    #pragma unroll
    for (int k = 0; k < 4; k++) {
        int ls = l - 3 + k;
        if (ls >= 0)
            s += cw[d * 4 + k] * __bfloat162float(xp[(ptrdiff_t)(k - 3) * (2 * DIN)]);
    }
    float sv = s / (1.0f + __expf(-s));
    g_ubf[idx] = __float2bfloat16(sv);
}

// ---------------------------------------------------------------------------
// Scan pass 1: per-chunk local scan (h0=0) -> h_out, sum_dt.
// 256 thr = 16 channel-groups x 16 states. Grid (DIN/16, NCH, B).
// ---------------------------------------------------------------------------
__global__ __launch_bounds__(256)
void scan_pass1(const float* __restrict__ A_log) {
    __shared__ float sdt[CLEN * 16], su[CLEN * 16], sB[CLEN * 16];
    const int tid = threadIdx.x;
    const int n = tid & 15, g = tid >> 4;
    const int d0 = blockIdx.x * 16, c = blockIdx.y, b = blockIdx.z;
    const size_t tokbase = (size_t)b * LSEQ + c * CLEN;

    for (int idx = tid; idx < CLEN * 16; idx += 256) {
        int l = idx >> 4, dd = idx & 15;
        size_t row = tokbase + l;
        sdt[idx] = __bfloat162float(g_dtb[row * DIN + d0 + dd]);
        su[idx]  = __bfloat162float(g_ubf[row * DIN + d0 + dd]);
        sB[idx]  = g_dbc[row * DBC_LD + 24 + dd];
    }
    __syncthreads();

    const int d = d0 + g;
    const float An = -__expf(A_log[d * DST + n]);
    float h = 0.f, sum = 0.f;
    #pragma unroll 4
    for (int l = 0; l < CLEN; l++) {
        float dt = sdt[l * 16 + g];
        float uu = su[l * 16 + g];
        float B  = sB[l * 16 + n];
        h = h * __expf(dt * An) + (dt * uu) * B;
        sum += dt;
    }
    size_t idxc = ((size_t)(b * NCH + c) * DIN + d);
    g_hout[idxc * DST + n] = h;
    if (n == 0) g_sdt[idxc] = sum;
}

// ---------------------------------------------------------------------------
// Scan pass 3: chunk-boundary state composed in-block (<=7 steps), then full
// per-chunk scan with fused y-reduction, D-skip, SiLU gate; bf16 writeout.
// ---------------------------------------------------------------------------
__global__ __launch_bounds__(256)
void scan_pass3(const float* __restrict__ A_log, const float* __restrict__ Dp) {
    __shared__ float sdt[CLEN * 16], su[CLEN * 16], sB[CLEN * 16],
                     sC[CLEN * 16], sy[CLEN * 16];
    const int tid = threadIdx.x;
    const int n = tid & 15, g = tid >> 4;
    const int d0 = blockIdx.x * 16, c = blockIdx.y, b = blockIdx.z;
    const size_t tokbase = (size_t)b * LSEQ + c * CLEN;

    for (int idx = tid; idx < CLEN * 16; idx += 256) {
        int l = idx >> 4, dd = idx & 15;
        size_t row = tokbase + l;
        sdt[idx] = __bfloat162float(g_dtb[row * DIN + d0 + dd]);
        su[idx]  = __bfloat162float(g_ubf[row * DIN + d0 + dd]);
        sB[idx]  = g_dbc[row * DBC_LD + 24 + dd];
        sC[idx]  = g_dbc[row * DBC_LD + 24 + DST + dd];
    }
    __syncthreads();

    const int d = d0 + g;
    const float An = -__expf(A_log[d * DST + n]);
    const float Dd = Dp[d];

    // compose h_in from previous chunks (pass2 folded in)
    float h = 0.f;
    #pragma unroll
    for (int cc = 0; cc < NCH - 1; cc++) {
        if (cc < c) {
            size_t id2 = ((size_t)(b * NCH + cc) * DIN + d);
            h = g_hout[id2 * DST + n] + __expf(An * g_sdt[id2]) * h;
        }
    }

    for (int l = 0; l < CLEN; l++) {
        float dt = sdt[l * 16 + g];
        float uu = su[l * 16 + g];
        float B  = sB[l * 16 + n];
        float Ct = sC[l * 16 + n];
        h = h * __expf(dt * An) + (dt * uu) * B;
        float p = h * Ct;
        p += __shfl_xor_sync(0xffffffffu, p, 8);
        p += __shfl_xor_sync(0xffffffffu, p, 4);
        p += __shfl_xor_sync(0xffffffffu, p, 2);
        p += __shfl_xor_sync(0xffffffffu, p, 1);
        if (n == 0) sy[l * 16 + g] = p + uu * Dd;
    }
    __syncthreads();

    for (int idx = tid; idx < CLEN * 16; idx += 256) {
        int l = idx >> 4, dd = idx & 15;
        size_t row = tokbase + l;
        float z = __bfloat162float(g_xzb[row * (2 * DIN) + DIN + d0 + dd]);
        float y = sy[idx] * (z / (1.0f + __expf(-z)));
        g_y[row * DIN + d0 + dd] = __float2bfloat16(y);
    }
}

// ---------------------------------------------------------------------------
// Epilogue: out[b,c,l] = g_ob[b*L+l, c] + x[b,c,l]
// ---------------------------------------------------------------------------
__global__ __launch_bounds__(256)
void epilogue_kernel(const float* __restrict__ x, float* __restrict__ out) {
    __shared__ float t[32 * 33];
    const int b  = blockIdx.z;
    const int c0 = blockIdx.y * 32;
    const int l0 = blockIdx.x * 32;
    const int tid = threadIdx.x;
    #pragma unroll
    for (int i = 0; i < 4; i++) {
        int idx = tid + i * 256;
        int lr = idx >> 5, c = idx & 31;
        t[c * 33 + lr] =
            __bfloat162float(g_ob[((size_t)b * LSEQ + l0 + lr) * CCH + c0 + c]);
    }
    __syncthreads();
    #pragma unroll
    for (int i = 0; i < 4; i++) {
        int idx = tid + i * 256;
        int cr = idx >> 5, l = idx & 31;
        size_t oi = ((size_t)b * CCH + c0 + cr) * LSEQ + l0 + l;
        out[oi] = t[cr * 33 + l] + x[oi];
    }
}

// ---------------------------------------------------------------------------
// Launch — 10 kernels, graph-capturable.
// ---------------------------------------------------------------------------
extern "C" void kernel_launch(void* const* d_in, const int* in_sizes, int n_in,
                              void* d_out, int out_size) {
    const float* x         = (const float*)d_in[0];
    const float* ln_w      = (const float*)d_in[1];
    const float* ln_b      = (const float*)d_in[2];
    const float* in_proj_w = (const float*)d_in[3];
    const float* conv_w    = (const float*)d_in[4];
    const float* conv_b    = (const float*)d_in[5];
    const float* x_proj_w  = (const float*)d_in[6];
    const float* dt_proj_w = (const float*)d_in[7];
    const float* dt_proj_b = (const float*)d_in[8];
    const float* A_log     = (const float*)d_in[9];
    const float* Dp        = (const float*)d_in[10];
    const float* out_proj_w= (const float*)d_in[11];
    float* out = (float*)d_out;
    (void)in_sizes; (void)n_in; (void)out_size;

    convert_weights<<<(2 * DIN * CCH + 255) / 256, 256>>>(in_proj_w, out_proj_w,
                                                          x_proj_w, dt_proj_w);
    ln_kernel<<<dim3(LSEQ / 16, BATCH), 256>>>(x, ln_w, ln_b);
    gemm_tc<0><<<dim3(2 * DIN / GBN, MTOK / GBM), 256>>>(nullptr);
    conv_silu_kernel<<<MTOK * DIN / 256, 256>>>(conv_w, conv_b);
    gemm_tc<1><<<dim3(DBC_LD / GBN, MTOK / GBM), 256>>>(nullptr);
    gemm_tc<2><<<dim3(DIN / GBN, MTOK / GBM), 256>>>(dt_proj_b);
    scan_pass1<<<dim3(DIN / 16, NCH, BATCH), 256>>>(A_log);
    scan_pass3<<<dim3(DIN / 16, NCH, BATCH), 256>>>(A_log, Dp);
    gemm_tc<3><<<dim3(CCH / GBN, MTOK / GBM), 256>>>(nullptr);
    epilogue_kernel<<<dim3(LSEQ / 32, CCH / 32, BATCH), 256>>>(x, out);
}